// round 13
// baseline (speedup 1.0000x reference)
#include <cuda_runtime.h>
#include <cuda_bf16.h>
#include <math.h>
#include <stdint.h>

#define Mr 32768
#define GDc 384
#define NFFT 16384
#define HALFN 8192
#define SCALE_U (1.0f / (16384.0f * 16384.0f))

__device__ __forceinline__ int PD(int e) { return e + (e >> 4) + (e >> 8); }

__device__ __forceinline__ float2 cmul(float2 a, float2 b) {
    return make_float2(a.x * b.x - a.y * b.y, a.x * b.y + a.y * b.x);
}
__device__ __forceinline__ float2 cadd(float2 a, float2 b) { return make_float2(a.x + b.x, a.y + b.y); }
__device__ __forceinline__ float2 csub(float2 a, float2 b) { return make_float2(a.x - b.x, a.y - b.y); }

__device__ __forceinline__ void fwd4(float2& x0, float2& x1, float2& x2, float2& x3, float2 W1) {
    float2 W2 = make_float2(W1.y, -W1.x);
    float2 W3 = cmul(W1, W1);
    float2 t02p = cadd(x0, x2), t02m = cmul(csub(x0, x2), W1);
    float2 t13p = cadd(x1, x3), t13m = cmul(csub(x1, x3), W2);
    x0 = cadd(t02p, t13p);
    x1 = cmul(csub(t02p, t13p), W3);
    x2 = cadd(t02m, t13m);
    x3 = cmul(csub(t02m, t13m), W3);
}
__device__ __forceinline__ void inv4(float2& x0, float2& x1, float2& x2, float2& x3, float2 w) {
    float2 cw2 = make_float2(w.x, -w.y);
    float2 cw1 = cmul(cw2, cw2);
    float2 cw3 = make_float2(-cw2.y, cw2.x);
    float2 b1 = cmul(x1, cw1), b3 = cmul(x3, cw1);
    float2 u0 = cadd(x0, b1), u1 = csub(x0, b1);
    float2 u2 = cadd(x2, b3), u3 = csub(x2, b3);
    float2 c2 = cmul(u2, cw2), c3 = cmul(u3, cw3);
    x0 = cadd(u0, c2); x2 = csub(u0, c2);
    x1 = cadd(u1, c3); x3 = csub(u1, c3);
}

// ---- tensor-core helpers ----
__device__ __forceinline__ void ldm4(uint32_t* r, const void* p) {
    uint32_t a = (uint32_t)__cvta_generic_to_shared(p);
    asm volatile("ldmatrix.sync.aligned.m8n8.x4.shared.b16 {%0,%1,%2,%3}, [%4];"
                 : "=r"(r[0]), "=r"(r[1]), "=r"(r[2]), "=r"(r[3]) : "r"(a));
}
__device__ __forceinline__ void ldm4t(uint32_t* r, const void* p) {
    uint32_t a = (uint32_t)__cvta_generic_to_shared(p);
    asm volatile("ldmatrix.sync.aligned.m8n8.x4.trans.shared.b16 {%0,%1,%2,%3}, [%4];"
                 : "=r"(r[0]), "=r"(r[1]), "=r"(r[2]), "=r"(r[3]) : "r"(a));
}
__device__ __forceinline__ void mmabf(float* c, const uint32_t* a, const uint32_t* b) {
    asm volatile("mma.sync.aligned.m16n8k16.row.col.f32.bf16.bf16.f32 "
                 "{%0,%1,%2,%3}, {%4,%5,%6,%7}, {%8,%9}, {%0,%1,%2,%3};"
                 : "+f"(c[0]), "+f"(c[1]), "+f"(c[2]), "+f"(c[3])
                 : "r"(a[0]), "r"(a[1]), "r"(a[2]), "r"(a[3]), "r"(b[0]), "r"(b[1]));
}
__device__ __forceinline__ void cpa16(void* dst, const void* src) {
    uint32_t d = (uint32_t)__cvta_generic_to_shared(dst);
    asm volatile("cp.async.ca.shared.global [%0], [%1], 16;" :: "r"(d), "l"(src));
}
#define CP_COMMIT asm volatile("cp.async.commit_group;")

// ---------------- scratch (device globals) ----------------
__device__ float  g_x   [(long long)Mr * GDc];          // emb @ W_proj [B,S,384] (f32, conv input)
__device__ float  g_hT  [(long long)4 * 2 * 128 * 8192];
__device__ float2 g_tw  [HALFN];
// bf16 hi/lo planes
__device__ __nv_bfloat16 g_WpH[128 * 384], g_WpL[128 * 384];
__device__ __nv_bfloat16 g_W1H[128 * 128], g_W1L[128 * 128];
__device__ __nv_bfloat16 g_W2H[128 * 256], g_W2L[128 * 256];
__device__ __nv_bfloat16 g_opH[128 * 128], g_opL[128 * 128];
__device__ __nv_bfloat16 g_eH [(long long)Mr * 128], g_eL[(long long)Mr * 128];
__device__ __nv_bfloat16 g_tH [(long long)Mr * 128], g_tL[(long long)Mr * 128];
__device__ __nv_bfloat16 g_hmH[(long long)Mr * 128], g_hmL[(long long)Mr * 128];
__device__ __nv_bfloat16 g_vH [(long long)4 * 128 * 8192], g_vL[(long long)4 * 128 * 8192];

// ---------------- twiddles ----------------
__global__ void k_twiddle() {
    int k = blockIdx.x * 256 + threadIdx.x;
    double a = -2.0 * 3.14159265358979323846 * (double)k / (double)NFFT;
    g_tw[k] = make_float2((float)cos(a), (float)sin(a));
}

// ---------------- weight pre-split ----------------
__global__ void k_prep(const float* __restrict__ Wp, const float* __restrict__ W1,
                       const float* __restrict__ W2, const float* __restrict__ op) {
    int i = blockIdx.x * 256 + threadIdx.x;
    float v; __nv_bfloat16 *H, *L; int j;
    if (i < 49152)      { j = i;          v = Wp[j]; H = g_WpH; L = g_WpL; }
    else if (i < 65536) { j = i - 49152;  v = W1[j]; H = g_W1H; L = g_W1L; }
    else if (i < 98304) { j = i - 65536;  v = W2[j]; H = g_W2H; L = g_W2L; }
    else                { j = i - 98304;  v = op[j]; H = g_opH; L = g_opL; }
    __nv_bfloat16 h = __float2bfloat16_rn(v);
    H[j] = h;
    L[j] = __float2bfloat16_rn(v - __bfloat162float(h));
}

// ---------------- emb + rope plane production ----------------
__global__ void k_prep2(const float* __restrict__ emb, const int* __restrict__ pos) {
    int idx = blockIdx.x * blockDim.x + threadIdx.x;
    if (idx >= Mr * 64) return;
    int j  = idx & 63;
    int bs = idx >> 6;
    float2 xv = *(const float2*)(emb + (size_t)bs * 128 + 2 * j);
    size_t o = (size_t)bs * 128 + 2 * j;
    {
        __nv_bfloat16 h0 = __float2bfloat16_rn(xv.x);
        __nv_bfloat16 h1 = __float2bfloat16_rn(xv.y);
        *(ushort2*)(g_eH + o) = make_ushort2(__bfloat16_as_ushort(h0), __bfloat16_as_ushort(h1));
        *(ushort2*)(g_eL + o) = make_ushort2(
            __bfloat16_as_ushort(__float2bfloat16_rn(xv.x - __bfloat162float(h0))),
            __bfloat16_as_ushort(__float2bfloat16_rn(xv.y - __bfloat162float(h1))));
    }
    float theta = exp2f(-(float)j * 0.20762050593046015f);
    float ang = (float)pos[bs] * theta;
    float sa, ca; sincosf(ang, &sa, &ca);
    float te = xv.x * ca - xv.y * sa;
    float to = xv.x * sa + xv.y * ca;
    {
        __nv_bfloat16 h0 = __float2bfloat16_rn(te);
        __nv_bfloat16 h1 = __float2bfloat16_rn(to);
        *(ushort2*)(g_tH + o) = make_ushort2(__bfloat16_as_ushort(h0), __bfloat16_as_ushort(h1));
        *(ushort2*)(g_tL + o) = make_ushort2(
            __bfloat16_as_ushort(__float2bfloat16_rn(te - __bfloat162float(h0))),
            __bfloat16_as_ushort(__float2bfloat16_rn(to - __bfloat162float(h1))));
    }
}

// ---------------- tensor-core GEMMs (bf16 3-term split, 4-stage async pipeline) ----------------
// MODE 0: g_x = emb @ W_proj (NC=384)   MODE 1: hmid planes (NC=128)
// MODE 2: g_hT (NC=256, transp)         MODE 3: out = v^T @ op (A k-major, NC=128)
#define STG 21504
#define AHo 0
#define ALo 6144
#define BHo 12288
#define BLo 16896
#define NSTAGE 4

template<int MODE>
__global__ __launch_bounds__(256, 2)
void k_mma(const float* __restrict__ bias, const float* __restrict__ gain,
           const float* __restrict__ beta, float* __restrict__ Cext)
{
    constexpr int NC = (MODE == 0) ? 384 : (MODE == 2) ? 256 : 128;
    extern __shared__ char dsm[];

    const int tid = threadIdx.x;
    const int m0  = blockIdx.x * 128;
    const int n0  = blockIdx.y * 128;
    const int wid = tid >> 5, lid = tid & 31;
    const int wm  = wid >> 2, wn = wid & 3;

    const __nv_bfloat16 *WH, *WL;
    if      (MODE == 0) { WH = g_WpH; WL = g_WpL; }
    else if (MODE == 1) { WH = g_W1H; WL = g_W1L; }
    else if (MODE == 2) { WH = g_W2H; WL = g_W2L; }
    else                { WH = g_opH; WL = g_opL; }

    const __nv_bfloat16 *AHp, *ALp;
    if      (MODE == 0) { AHp = g_eH;  ALp = g_eL;  }
    else if (MODE == 1) { AHp = g_tH;  ALp = g_tL;  }
    else if (MODE == 2) { AHp = g_hmH; ALp = g_hmL; }
    else {
        size_t off = (size_t)(m0 >> 13) * (128 * 8192) + (m0 & 8191);
        AHp = g_vH + off; ALp = g_vL + off;
    }

    float acc[4][4][4];
#pragma unroll
    for (int mi = 0; mi < 4; mi++)
#pragma unroll
        for (int ni = 0; ni < 4; ni++)
#pragma unroll
            for (int q = 0; q < 4; q++) acc[mi][ni][q] = 0.f;

    const int arow = tid >> 1, akh = (tid & 1) * 8;
    const int krow = tid >> 4, nq8 = (tid & 15) * 8;

    auto issue = [&](int kt, int s) {
        char* sb = dsm + s * STG;
        cpa16(sb + BHo + krow * 272 + nq8 * 2, WH + (size_t)(kt + krow) * NC + n0 + nq8);
        cpa16(sb + BLo + krow * 272 + nq8 * 2, WL + (size_t)(kt + krow) * NC + n0 + nq8);
        if (MODE == 3) {
            cpa16(sb + AHo + krow * 272 + nq8 * 2, AHp + (size_t)(kt + krow) * 8192 + nq8);
            cpa16(sb + ALo + krow * 272 + nq8 * 2, ALp + (size_t)(kt + krow) * 8192 + nq8);
        } else {
            cpa16(sb + AHo + arow * 48 + akh * 2, AHp + (size_t)(m0 + arow) * 128 + kt + akh);
            cpa16(sb + ALo + arow * 48 + akh * 2, ALp + (size_t)(m0 + arow) * 128 + kt + akh);
        }
    };

    auto compute = [&](int s) {
        char* sb = dsm + s * STG;
        uint32_t Ah[4][4], Al[4][4];
        if (MODE != 3) {
            int ar = wm * 64 + (lid & 15);
            int ac = ((lid >> 4) & 1) * 16;
#pragma unroll
            for (int mi = 0; mi < 4; mi++) {
                ldm4(Ah[mi], sb + AHo + (ar + mi * 16) * 48 + ac);
                ldm4(Al[mi], sb + ALo + (ar + mi * 16) * 48 + ac);
            }
        } else {
            int kr = ((lid >> 4) & 1) * 8 + (lid & 7);
            int mc = wm * 64 + ((lid >> 3) & 1) * 8;
#pragma unroll
            for (int mi = 0; mi < 4; mi++) {
                ldm4t(Ah[mi], sb + AHo + kr * 272 + (mc + mi * 16) * 2);
                ldm4t(Al[mi], sb + ALo + kr * 272 + (mc + mi * 16) * 2);
            }
        }
        int kr = ((lid >> 3) & 1) * 8 + (lid & 7);
        int ncb = wn * 32 + ((lid >> 4) & 1) * 8;
#pragma unroll
        for (int p = 0; p < 2; p++) {
            uint32_t Bh[4], Bl[4];
            ldm4t(Bh, sb + BHo + kr * 272 + (ncb + p * 16) * 2);
            ldm4t(Bl, sb + BLo + kr * 272 + (ncb + p * 16) * 2);
#pragma unroll
            for (int q = 0; q < 2; q++) {
                int ni = p * 2 + q;
#pragma unroll
                for (int mi = 0; mi < 4; mi++) {
                    mmabf(acc[mi][ni], Ah[mi], Bh + 2 * q);
                    mmabf(acc[mi][ni], Ah[mi], Bl + 2 * q);
                    mmabf(acc[mi][ni], Al[mi], Bh + 2 * q);
                }
            }
        }
    };

    // 4-stage pipeline: 3 chunks in flight
    issue(0, 0);  CP_COMMIT;
    issue(16, 1); CP_COMMIT;
    issue(32, 2); CP_COMMIT;
#pragma unroll 1
    for (int c = 0; c < 8; c++) {
        if (c <= 5)      asm volatile("cp.async.wait_group 2;" ::: "memory");
        else if (c == 6) asm volatile("cp.async.wait_group 1;" ::: "memory");
        else             asm volatile("cp.async.wait_group 0;" ::: "memory");
        __syncthreads();
        if (c < 5) { issue((c + 3) * 16, (c + 3) & 3); CP_COMMIT; }
        compute(c & 3);
    }
    __syncthreads();

    // ---------------- epilogues ----------------
    if (MODE == 0 || MODE == 3) {
        float* C = (MODE == 0) ? g_x : Cext;
#pragma unroll
        for (int mi = 0; mi < 4; mi++)
#pragma unroll
            for (int ni = 0; ni < 4; ni++) {
                int r0 = m0 + wm * 64 + mi * 16 + (lid >> 2);
                int cc = n0 + wn * 32 + ni * 8 + 2 * (lid & 3);
                *(float2*)(C + (size_t)r0 * NC + cc)       = make_float2(acc[mi][ni][0], acc[mi][ni][1]);
                *(float2*)(C + (size_t)(r0 + 8) * NC + cc) = make_float2(acc[mi][ni][2], acc[mi][ni][3]);
            }
        return;
    }

    float* Ep = (float*)dsm;
#pragma unroll
    for (int mi = 0; mi < 4; mi++)
#pragma unroll
        for (int ni = 0; ni < 4; ni++) {
            int r0 = wm * 64 + mi * 16 + (lid >> 2);
            int cc = wn * 32 + ni * 8 + 2 * (lid & 3);
            Ep[r0 * 129 + cc]           = acc[mi][ni][0];
            Ep[r0 * 129 + cc + 1]       = acc[mi][ni][1];
            Ep[(r0 + 8) * 129 + cc]     = acc[mi][ni][2];
            Ep[(r0 + 8) * 129 + cc + 1] = acc[mi][ni][3];
        }
    __syncthreads();

    int row = tid >> 1, half = tid & 1;
    float* rp = Ep + row * 129 + half * 64;

    if (MODE == 1) {
        float s = 0.f, s2 = 0.f;
#pragma unroll 4
        for (int i = 0; i < 64; i++) {
            float x = rp[i] + bias[half * 64 + i];
            s += x; s2 += x * x;
        }
        s  += __shfl_xor_sync(0xffffffffu, s,  1);
        s2 += __shfl_xor_sync(0xffffffffu, s2, 1);
        float mu  = s * (1.f / 128.f);
        float var = s2 * (1.f / 128.f) - mu * mu;
        float rs  = rsqrtf(var + 1e-5f);
        __nv_bfloat16* oH = g_hmH + (size_t)(m0 + row) * 128 + half * 64;
        __nv_bfloat16* oL = g_hmL + (size_t)(m0 + row) * 128 + half * 64;
#pragma unroll 1
        for (int i = 0; i < 16; i++) {
            __nv_bfloat16 hb[4], lb[4];
#pragma unroll
            for (int j = 0; j < 4; j++) {
                int cc = half * 64 + i * 4 + j;
                float x  = rp[i * 4 + j] + bias[cc];
                float xn = (x - mu) * rs * gain[cc] + beta[cc];
                float o  = 0.5f * xn * (1.f + erff(xn * 0.70710678118654752f));
                __nv_bfloat16 hh = __float2bfloat16_rn(o);
                hb[j] = hh;
                lb[j] = __float2bfloat16_rn(o - __bfloat162float(hh));
            }
            *(uint2*)(oH + i * 4) = *(uint2*)hb;
            *(uint2*)(oL + i * 4) = *(uint2*)lb;
        }
    } else { // MODE 2
        float s = 0.f;
#pragma unroll 4
        for (int i = 0; i < 64; i++) {
            int gc = n0 + half * 64 + i;
            float x = (rp[i] + bias[gc]) * gain[gc];
            s += fabsf(x);
        }
        s += __shfl_xor_sync(0xffffffffu, s, 1);
        float rsc = 1.f / (s + 1e-8f);
#pragma unroll 4
        for (int i = 0; i < 64; i++) {
            int gc = n0 + half * 64 + i;
            rp[i] = (rp[i] + bias[gc]) * gain[gc] * rsc;
        }
        __syncthreads();
        float* dst = g_hT + (size_t)((m0 >> 13) * 2 + (n0 >> 7)) * (128 * 8192) + (m0 & 8191);
#pragma unroll 1
        for (int ccs = 0; ccs < 16; ccs++) {
            int cc = wid * 16 + ccs;
            float* dp = dst + (size_t)cc * 8192;
#pragma unroll
            for (int sq = 0; sq < 4; sq++)
                dp[sq * 32 + lid] = Ep[(sq * 32 + lid) * 129 + cc];
        }
    }
}

// ---------------- FFT recurrence + fused depthwise conv ----------------
__global__ __launch_bounds__(1024, 1)
void k_fftrec(const float* __restrict__ Bp, const float* __restrict__ cw,
              const float* __restrict__ cb) {
    extern __shared__ float2 sh[];
    __shared__ float s_w[1152];
    __shared__ float s_b[384];
    int b = blockIdx.x >> 7, d = blockIdx.x & 127;
    int t = threadIdx.x;
    if (t < 384) s_b[t] = cb[t];
    if (t >= 512 && t < 512 + 384) {
        int i = t - 512;
        s_w[i] = cw[i]; s_w[i + 384] = cw[i + 384]; s_w[i + 768] = cw[i + 768];
    }
    __syncthreads();

    const float* X = g_x + (size_t)b * (8192 * 384);
    const int fbase = d * 24576;
    const int FMAX = 8192 * 384;

    auto ztap = [&](int j) -> float {
        int f = fbase + j;
        int c = j % 384;
        float a = s_b[c] + s_w[3 * c + 1] * X[f];
        if (f >= 384)       a += s_w[3 * c]     * X[f - 384];
        if (f + 384 < FMAX) a += s_w[3 * c + 2] * X[f + 384];
        return a;
    };

    float vv[8];
#pragma unroll
    for (int k = 0; k < 8; k++) vv[k] = ztap(16384 + t + k * 1024);

    for (int it = 0; it < 2; it++) {
        const float* h = g_hT + (size_t)((b * 2 + it) * 128 + d) * 8192;

        // F1: radix-16 (lg13+lg11), fused with pack+zero-pad
        {
            float2 x[16];
#pragma unroll
            for (int r = 0; r < 4; r++) {
                float2 x0 = make_float2(vv[r],     h[t + 1024 * r]);
                float2 x1 = make_float2(vv[r + 4], h[t + 1024 * r + 4096]);
                float2 W1 = g_tw[t + 1024 * r];
                float2 W2 = make_float2(W1.y, -W1.x);
                float2 W3 = cmul(W1, W1);
                float2 t02m = cmul(x0, W1);
                float2 t13m = cmul(x1, W2);
                x[r]      = cadd(x0, x1);
                x[r + 4]  = cmul(csub(x0, x1), W3);
                x[r + 8]  = cadd(t02m, t13m);
                x[r + 12] = cmul(csub(t02m, t13m), W3);
            }
            float2 Wl2 = g_tw[4 * t];
#pragma unroll
            for (int q = 0; q < 4; q++) fwd4(x[4 * q], x[4 * q + 1], x[4 * q + 2], x[4 * q + 3], Wl2);
#pragma unroll
            for (int r = 0; r < 16; r++) sh[PD(t + 1024 * r)] = x[r];
        }
        __syncthreads();

        // F2: radix-16 (lg9+lg7)
        {
            int blk = t >> 6, off = t & 63;
            int base = blk * 1024 + off;
            float2 x[16];
#pragma unroll
            for (int r = 0; r < 16; r++) x[r] = sh[PD(base + 64 * r)];
#pragma unroll
            for (int r = 0; r < 4; r++) fwd4(x[r], x[r + 4], x[r + 8], x[r + 12], g_tw[16 * off + 1024 * r]);
            float2 Wl2 = g_tw[64 * off];
#pragma unroll
            for (int q = 0; q < 4; q++) fwd4(x[4 * q], x[4 * q + 1], x[4 * q + 2], x[4 * q + 3], Wl2);
#pragma unroll
            for (int r = 0; r < 16; r++) sh[PD(base + 64 * r)] = x[r];
        }
        __syncthreads();

        // F3: radix-16 (lg5+lg3)
        {
            int blk = t >> 2, off = t & 3;
            int base = blk * 64 + off;
            float2 x[16];
#pragma unroll
            for (int r = 0; r < 16; r++) x[r] = sh[PD(base + 4 * r)];
#pragma unroll
            for (int r = 0; r < 4; r++) fwd4(x[r], x[r + 4], x[r + 8], x[r + 12], g_tw[256 * off + 1024 * r]);
            float2 Wl2 = g_tw[1024 * off];
#pragma unroll
            for (int q = 0; q < 4; q++) fwd4(x[4 * q], x[4 * q + 1], x[4 * q + 2], x[4 * q + 3], Wl2);
#pragma unroll
            for (int r = 0; r < 16; r++) sh[PD(base + 4 * r)] = x[r];
        }
        __syncthreads();

        // F4: radix-4 (lg1)
#pragma unroll
        for (int k = 0; k < 4; k++) {
            int q4 = (t + 1024 * k) * 4;
            float2 y0 = sh[PD(q4)], y1 = sh[PD(q4 + 1)], y2 = sh[PD(q4 + 2)], y3 = sh[PD(q4 + 3)];
            fwd4(y0, y1, y2, y3, make_float2(1.f, 0.f));
            sh[PD(q4)] = y0; sh[PD(q4 + 1)] = y1; sh[PD(q4 + 2)] = y2; sh[PD(q4 + 3)] = y3;
        }
        __syncthreads();

        // spectral multiply + I1 (lg0+lg2)
        {
            int e0 = t << 4;
            float2 x[16];
#pragma unroll
            for (int r = 0; r < 16; r++) x[r] = sh[PD(e0 + r)];
#pragma unroll
            for (int r = 0; r < 16; r++) {
                int p  = e0 + r;
                int kk = __brev(p) >> 18;
                int k2 = (16384 - kk) & 16383;
                int p2 = __brev(k2) >> 18;
                float2 Q = sh[PD(p2)];
                float2 P = x[r];
                float vx = 0.5f * (P.x + Q.x), vy = 0.5f * (P.y - Q.y);
                float hx = 0.5f * (P.y + Q.y), hy = 0.5f * (Q.x - P.x);
                x[r] = make_float2(vx * hx - vy * hy, vx * hy + vy * hx);
            }
#pragma unroll
            for (int q = 0; q < 4; q++) inv4(x[4 * q], x[4 * q + 1], x[4 * q + 2], x[4 * q + 3], make_float2(1.f, 0.f));
#pragma unroll
            for (int r = 0; r < 4; r++) inv4(x[r], x[r + 4], x[r + 8], x[r + 12], g_tw[1024 * r]);
            __syncthreads();
#pragma unroll
            for (int r = 0; r < 16; r++) sh[PD(e0 + r)] = x[r];
        }
        __syncthreads();

        // I2: radix-16 (lg4+lg6)
        {
            int blk = t >> 4, off = t & 15;
            int base = blk * 256 + off;
            float2 x[16];
#pragma unroll
            for (int r = 0; r < 16; r++) x[r] = sh[PD(base + 16 * r)];
            float2 wA = g_tw[256 * off];
#pragma unroll
            for (int q = 0; q < 4; q++) inv4(x[4 * q], x[4 * q + 1], x[4 * q + 2], x[4 * q + 3], wA);
#pragma unroll
            for (int r = 0; r < 4; r++) inv4(x[r], x[r + 4], x[r + 8], x[r + 12], g_tw[64 * off + 1024 * r]);
#pragma unroll
            for (int r = 0; r < 16; r++) sh[PD(base + 16 * r)] = x[r];
        }
        __syncthreads();

        // I3: radix-16 (lg8+lg10)
        {
            int blk = t >> 8, off = t & 255;
            int base = blk * 4096 + off;
            float2 x[16];
#pragma unroll
            for (int r = 0; r < 16; r++) x[r] = sh[PD(base + 256 * r)];
            float2 wA = g_tw[16 * off];
#pragma unroll
            for (int q = 0; q < 4; q++) inv4(x[4 * q], x[4 * q + 1], x[4 * q + 2], x[4 * q + 3], wA);
#pragma unroll
            for (int r = 0; r < 4; r++) inv4(x[r], x[r + 4], x[r + 8], x[r + 12], g_tw[4 * off + 1024 * r]);
#pragma unroll
            for (int r = 0; r < 16; r++) sh[PD(base + 256 * r)] = x[r];
        }
        __syncthreads();

        // I4: final radix-4 (lg12) fused with conv(z) + v-update
        {
            float Bn = Bp[it * 128 + d];
#pragma unroll
            for (int jj = 0; jj < 4; jj++) {
                int j = t + jj * 1024;
                float2 x0 = sh[PD(j)];
                float2 x1 = sh[PD(j + 4096)];
                float2 x2 = sh[PD(j + 8192)];
                float2 x3 = sh[PD(j + 12288)];
                float2 w   = g_tw[j];
                float2 cw2 = make_float2(w.x, -w.y);
                float2 cw1 = cmul(cw2, cw2);
                float2 cw3 = make_float2(-cw2.y, cw2.x);
                float2 b1 = cmul(x1, cw1);
                float2 b3 = cmul(x3, cw1);
                float2 u0 = cadd(x0, b1), u1 = csub(x0, b1);
                float2 u2 = cadd(x2, b3), u3 = csub(x2, b3);
                float y0x = u0.x + (u2.x * cw2.x - u2.y * cw2.y);
                float y1x = u1.x + (u3.x * cw3.x - u3.y * cw3.y);
                float z0 = ztap(it * 8192 + j);
                float z1 = ztap(it * 8192 + j + 4096);
                vv[jj]     = z0 * (y0x * SCALE_U + Bn * vv[jj]);
                vv[jj + 4] = z1 * (y1x * SCALE_U + Bn * vv[jj + 4]);
            }
        }
        __syncthreads();
    }
    __nv_bfloat16* vH = g_vH + (size_t)(b * 128 + d) * 8192;
    __nv_bfloat16* vL = g_vL + (size_t)(b * 128 + d) * 8192;
#pragma unroll
    for (int k = 0; k < 8; k++) {
        float val = vv[k];
        __nv_bfloat16 hh = __float2bfloat16_rn(val);
        vH[t + k * 1024] = hh;
        vL[t + k * 1024] = __float2bfloat16_rn(val - __bfloat162float(hh));
    }
}

extern "C" void kernel_launch(void* const* d_in, const int* in_sizes, int n_in,
                              void* d_out, int out_size) {
    const float* emb = (const float*)d_in[0];
    const float* Wp  = (const float*)d_in[1];
    const float* cw  = (const float*)d_in[2];
    const float* cb  = (const float*)d_in[3];
    const float* W1  = (const float*)d_in[4];
    const float* b1  = (const float*)d_in[5];
    const float* lng = (const float*)d_in[6];
    const float* lnb = (const float*)d_in[7];
    const float* W2  = (const float*)d_in[8];
    const float* b2  = (const float*)d_in[9];
    const float* ffs = (const float*)d_in[10];
    const float* op  = (const float*)d_in[11];
    const float* Bp  = (const float*)d_in[12];
    const int*   pos = (const int*)d_in[13];
    float* out = (float*)d_out;

    const int FFT_SMEM = 139776;
    const int MMA_SMEM = NSTAGE * STG;   // 86016 (all modes; epilogue reuses)
    cudaFuncSetAttribute(k_fftrec, cudaFuncAttributeMaxDynamicSharedMemorySize, FFT_SMEM);
    cudaFuncSetAttribute(k_mma<0>, cudaFuncAttributeMaxDynamicSharedMemorySize, MMA_SMEM);
    cudaFuncSetAttribute(k_mma<1>, cudaFuncAttributeMaxDynamicSharedMemorySize, MMA_SMEM);
    cudaFuncSetAttribute(k_mma<2>, cudaFuncAttributeMaxDynamicSharedMemorySize, MMA_SMEM);
    cudaFuncSetAttribute(k_mma<3>, cudaFuncAttributeMaxDynamicSharedMemorySize, MMA_SMEM);

    k_twiddle<<<32, 256>>>();
    k_prep<<<448, 256>>>(Wp, W1, W2, op);
    k_prep2<<<8192, 256>>>(emb, pos);
    k_mma<0><<<dim3(256, 3), 256, MMA_SMEM>>>(nullptr, nullptr, nullptr, nullptr);
    k_mma<1><<<dim3(256, 1), 256, MMA_SMEM>>>(b1, lng, lnb, nullptr);
    k_mma<2><<<dim3(256, 2), 256, MMA_SMEM>>>(b2, ffs, nullptr, nullptr);
    k_fftrec<<<512, 1024, FFT_SMEM>>>(Bp, cw, cb);
    k_mma<3><<<dim3(256, 1), 256, MMA_SMEM>>>(nullptr, nullptr, nullptr, out);
}

// round 15
// speedup vs baseline: 1.0594x; 1.0594x over previous
#include <cuda_runtime.h>
#include <cuda_bf16.h>
#include <math.h>
#include <stdint.h>

#define Mr 32768
#define GDc 384
#define NFFT 16384
#define HALFN 8192
#define SCALE_U (1.0f / (16384.0f * 16384.0f))

__device__ __forceinline__ int PD(int e) { return e + (e >> 4) + (e >> 8); }

__device__ __forceinline__ float2 cmul(float2 a, float2 b) {
    return make_float2(a.x * b.x - a.y * b.y, a.x * b.y + a.y * b.x);
}
__device__ __forceinline__ float2 cadd(float2 a, float2 b) { return make_float2(a.x + b.x, a.y + b.y); }
__device__ __forceinline__ float2 csub(float2 a, float2 b) { return make_float2(a.x - b.x, a.y - b.y); }

__device__ __forceinline__ void fwd4(float2& x0, float2& x1, float2& x2, float2& x3, float2 W1) {
    float2 W2 = make_float2(W1.y, -W1.x);
    float2 W3 = cmul(W1, W1);
    float2 t02p = cadd(x0, x2), t02m = cmul(csub(x0, x2), W1);
    float2 t13p = cadd(x1, x3), t13m = cmul(csub(x1, x3), W2);
    x0 = cadd(t02p, t13p);
    x1 = cmul(csub(t02p, t13p), W3);
    x2 = cadd(t02m, t13m);
    x3 = cmul(csub(t02m, t13m), W3);
}
__device__ __forceinline__ void inv4(float2& x0, float2& x1, float2& x2, float2& x3, float2 w) {
    float2 cw2 = make_float2(w.x, -w.y);
    float2 cw1 = cmul(cw2, cw2);
    float2 cw3 = make_float2(-cw2.y, cw2.x);
    float2 b1 = cmul(x1, cw1), b3 = cmul(x3, cw1);
    float2 u0 = cadd(x0, b1), u1 = csub(x0, b1);
    float2 u2 = cadd(x2, b3), u3 = csub(x2, b3);
    float2 c2 = cmul(u2, cw2), c3 = cmul(u3, cw3);
    x0 = cadd(u0, c2); x2 = csub(u0, c2);
    x1 = cadd(u1, c3); x3 = csub(u1, c3);
}

// ---- tensor-core helpers ----
__device__ __forceinline__ void ldm4(uint32_t* r, const void* p) {
    uint32_t a = (uint32_t)__cvta_generic_to_shared(p);
    asm volatile("ldmatrix.sync.aligned.m8n8.x4.shared.b16 {%0,%1,%2,%3}, [%4];"
                 : "=r"(r[0]), "=r"(r[1]), "=r"(r[2]), "=r"(r[3]) : "r"(a));
}
__device__ __forceinline__ void ldm4t(uint32_t* r, const void* p) {
    uint32_t a = (uint32_t)__cvta_generic_to_shared(p);
    asm volatile("ldmatrix.sync.aligned.m8n8.x4.trans.shared.b16 {%0,%1,%2,%3}, [%4];"
                 : "=r"(r[0]), "=r"(r[1]), "=r"(r[2]), "=r"(r[3]) : "r"(a));
}
__device__ __forceinline__ void mmabf(float* c, const uint32_t* a, const uint32_t* b) {
    asm volatile("mma.sync.aligned.m16n8k16.row.col.f32.bf16.bf16.f32 "
                 "{%0,%1,%2,%3}, {%4,%5,%6,%7}, {%8,%9}, {%0,%1,%2,%3};"
                 : "+f"(c[0]), "+f"(c[1]), "+f"(c[2]), "+f"(c[3])
                 : "r"(a[0]), "r"(a[1]), "r"(a[2]), "r"(a[3]), "r"(b[0]), "r"(b[1]));
}
__device__ __forceinline__ void cpa16(void* dst, const void* src) {
    uint32_t d = (uint32_t)__cvta_generic_to_shared(dst);
    asm volatile("cp.async.ca.shared.global [%0], [%1], 16;" :: "r"(d), "l"(src));
}
#define CP_COMMIT asm volatile("cp.async.commit_group;")
#define CP_WAIT0  asm volatile("cp.async.wait_group 0;" ::: "memory")

// ---------------- scratch (device globals) ----------------
__device__ float  g_x   [(long long)Mr * GDc];
__device__ float  g_hT  [(long long)4 * 2 * 128 * 8192];
__device__ float2 g_tw  [HALFN];
__device__ __nv_bfloat16 g_WpH[128 * 384], g_WpL[128 * 384];
__device__ __nv_bfloat16 g_W1H[128 * 128], g_W1L[128 * 128];
__device__ __nv_bfloat16 g_W2H[128 * 256], g_W2L[128 * 256];
__device__ __nv_bfloat16 g_opH[128 * 128], g_opL[128 * 128];
__device__ __nv_bfloat16 g_eH [(long long)Mr * 128], g_eL[(long long)Mr * 128];
__device__ __nv_bfloat16 g_tH [(long long)Mr * 128], g_tL[(long long)Mr * 128];
__device__ __nv_bfloat16 g_hmH[(long long)Mr * 128], g_hmL[(long long)Mr * 128];
__device__ __nv_bfloat16 g_vH [(long long)4 * 128 * 8192], g_vL[(long long)4 * 128 * 8192];

// ---------------- fused init: twiddles + weight split + emb/rope planes ----------------
__global__ void k_init(const float* __restrict__ emb, const int* __restrict__ pos,
                       const float* __restrict__ Wp, const float* __restrict__ W1,
                       const float* __restrict__ W2, const float* __restrict__ op) {
    int bx = blockIdx.x, t = threadIdx.x;
    if (bx < 32) {
        int k = bx * 256 + t;
        double a = -2.0 * 3.14159265358979323846 * (double)k / (double)NFFT;
        g_tw[k] = make_float2((float)cos(a), (float)sin(a));
        return;
    }
    if (bx < 480) {
        int i = (bx - 32) * 256 + t;
        float v; __nv_bfloat16 *H, *L; int j;
        if (i < 49152)      { j = i;          v = Wp[j]; H = g_WpH; L = g_WpL; }
        else if (i < 65536) { j = i - 49152;  v = W1[j]; H = g_W1H; L = g_W1L; }
        else if (i < 98304) { j = i - 65536;  v = W2[j]; H = g_W2H; L = g_W2L; }
        else                { j = i - 98304;  v = op[j]; H = g_opH; L = g_opL; }
        __nv_bfloat16 h = __float2bfloat16_rn(v);
        H[j] = h;
        L[j] = __float2bfloat16_rn(v - __bfloat162float(h));
        return;
    }
    int idx = (bx - 480) * 256 + t;
    int j  = idx & 63;
    int bs = idx >> 6;
    float2 xv = *(const float2*)(emb + (size_t)bs * 128 + 2 * j);
    size_t o = (size_t)bs * 128 + 2 * j;
    {
        __nv_bfloat16 h0 = __float2bfloat16_rn(xv.x);
        __nv_bfloat16 h1 = __float2bfloat16_rn(xv.y);
        *(ushort2*)(g_eH + o) = make_ushort2(__bfloat16_as_ushort(h0), __bfloat16_as_ushort(h1));
        *(ushort2*)(g_eL + o) = make_ushort2(
            __bfloat16_as_ushort(__float2bfloat16_rn(xv.x - __bfloat162float(h0))),
            __bfloat16_as_ushort(__float2bfloat16_rn(xv.y - __bfloat162float(h1))));
    }
    float theta = exp2f(-(float)j * 0.20762050593046015f);
    float ang = (float)pos[bs] * theta;
    float sa, ca; sincosf(ang, &sa, &ca);
    float te = xv.x * ca - xv.y * sa;
    float to = xv.x * sa + xv.y * ca;
    {
        __nv_bfloat16 h0 = __float2bfloat16_rn(te);
        __nv_bfloat16 h1 = __float2bfloat16_rn(to);
        *(ushort2*)(g_tH + o) = make_ushort2(__bfloat16_as_ushort(h0), __bfloat16_as_ushort(h1));
        *(ushort2*)(g_tL + o) = make_ushort2(
            __bfloat16_as_ushort(__float2bfloat16_rn(te - __bfloat162float(h0))),
            __bfloat16_as_ushort(__float2bfloat16_rn(to - __bfloat162float(h1))));
    }
}

// ---------------- bf16 3-term split GEMM body (mma.sync, 2-stage async) ----------------
// MODE 0: g_x = emb @ W_proj (NC=384)   MODE 1: hmid planes (NC=128)
// MODE 2: g_hT (NC=256, transp)         MODE 3: out = v^T @ op (A k-major, NC=128)
#define STG 21504
#define AHo 0
#define ALo 6144
#define BHo 12288
#define BLo 16896

extern __shared__ char dsm[];

template<int MODE>
__device__ __forceinline__
void mma_body(int bm, int bn, const float* __restrict__ bias,
              const float* __restrict__ gain, const float* __restrict__ beta,
              float* __restrict__ Cext)
{
    constexpr int NC = (MODE == 0) ? 384 : (MODE == 2) ? 256 : 128;
    const int tid = threadIdx.x;
    const int m0  = bm * 128;
    const int n0  = bn * 128;
    const int wid = tid >> 5, lid = tid & 31;
    const int wm  = wid >> 2, wn = wid & 3;

    const __nv_bfloat16 *WH, *WL;
    if      (MODE == 0) { WH = g_WpH; WL = g_WpL; }
    else if (MODE == 1) { WH = g_W1H; WL = g_W1L; }
    else if (MODE == 2) { WH = g_W2H; WL = g_W2L; }
    else                { WH = g_opH; WL = g_opL; }

    const __nv_bfloat16 *AHp, *ALp;
    if      (MODE == 0) { AHp = g_eH;  ALp = g_eL;  }
    else if (MODE == 1) { AHp = g_tH;  ALp = g_tL;  }
    else if (MODE == 2) { AHp = g_hmH; ALp = g_hmL; }
    else {
        size_t off = (size_t)(m0 >> 13) * (128 * 8192) + (m0 & 8191);
        AHp = g_vH + off; ALp = g_vL + off;
    }

    float acc[4][4][4];
#pragma unroll
    for (int mi = 0; mi < 4; mi++)
#pragma unroll
        for (int ni = 0; ni < 4; ni++)
#pragma unroll
            for (int q = 0; q < 4; q++) acc[mi][ni][q] = 0.f;

    const int arow = tid >> 1, akh = (tid & 1) * 8;
    const int krow = tid >> 4, nq8 = (tid & 15) * 8;

    auto issue = [&](int kt, int s) {
        char* sb = dsm + s * STG;
        cpa16(sb + BHo + krow * 272 + nq8 * 2, WH + (size_t)(kt + krow) * NC + n0 + nq8);
        cpa16(sb + BLo + krow * 272 + nq8 * 2, WL + (size_t)(kt + krow) * NC + n0 + nq8);
        if (MODE == 3) {
            cpa16(sb + AHo + krow * 272 + nq8 * 2, AHp + (size_t)(kt + krow) * 8192 + nq8);
            cpa16(sb + ALo + krow * 272 + nq8 * 2, ALp + (size_t)(kt + krow) * 8192 + nq8);
        } else {
            cpa16(sb + AHo + arow * 48 + akh * 2, AHp + (size_t)(m0 + arow) * 128 + kt + akh);
            cpa16(sb + ALo + arow * 48 + akh * 2, ALp + (size_t)(m0 + arow) * 128 + kt + akh);
        }
    };

    auto compute = [&](int s) {
        char* sb = dsm + s * STG;
        uint32_t Ah[4][4], Al[4][4];
        if (MODE != 3) {
            int ar = wm * 64 + (lid & 15);
            int ac = ((lid >> 4) & 1) * 16;
#pragma unroll
            for (int mi = 0; mi < 4; mi++) {
                ldm4(Ah[mi], sb + AHo + (ar + mi * 16) * 48 + ac);
                ldm4(Al[mi], sb + ALo + (ar + mi * 16) * 48 + ac);
            }
        } else {
            int kr = ((lid >> 4) & 1) * 8 + (lid & 7);
            int mc = wm * 64 + ((lid >> 3) & 1) * 8;
#pragma unroll
            for (int mi = 0; mi < 4; mi++) {
                ldm4t(Ah[mi], sb + AHo + kr * 272 + (mc + mi * 16) * 2);
                ldm4t(Al[mi], sb + ALo + kr * 272 + (mc + mi * 16) * 2);
            }
        }
        int kr = ((lid >> 3) & 1) * 8 + (lid & 7);
        int ncb = wn * 32 + ((lid >> 4) & 1) * 8;
#pragma unroll
        for (int p = 0; p < 2; p++) {
            uint32_t Bh[4], Bl[4];
            ldm4t(Bh, sb + BHo + kr * 272 + (ncb + p * 16) * 2);
            ldm4t(Bl, sb + BLo + kr * 272 + (ncb + p * 16) * 2);
#pragma unroll
            for (int q = 0; q < 2; q++) {
                int ni = p * 2 + q;
#pragma unroll
                for (int mi = 0; mi < 4; mi++) {
                    mmabf(acc[mi][ni], Ah[mi], Bh + 2 * q);
                    mmabf(acc[mi][ni], Ah[mi], Bl + 2 * q);
                    mmabf(acc[mi][ni], Al[mi], Bh + 2 * q);
                }
            }
        }
    };

    issue(0, 0); CP_COMMIT; CP_WAIT0;
    __syncthreads();
#pragma unroll 1
    for (int c = 0; c < 8; c++) {
        if (c < 7) { issue((c + 1) * 16, (c + 1) & 1); CP_COMMIT; }
        compute(c & 1);
        if (c < 7) CP_WAIT0;
        __syncthreads();
    }

    if (MODE == 0 || MODE == 3) {
        float* C = (MODE == 0) ? g_x : Cext;
#pragma unroll
        for (int mi = 0; mi < 4; mi++)
#pragma unroll
            for (int ni = 0; ni < 4; ni++) {
                int r0 = m0 + wm * 64 + mi * 16 + (lid >> 2);
                int cc = n0 + wn * 32 + ni * 8 + 2 * (lid & 3);
                *(float2*)(C + (size_t)r0 * NC + cc)       = make_float2(acc[mi][ni][0], acc[mi][ni][1]);
                *(float2*)(C + (size_t)(r0 + 8) * NC + cc) = make_float2(acc[mi][ni][2], acc[mi][ni][3]);
            }
        return;
    }

    float* Ep = (float*)dsm;
    __syncthreads();
#pragma unroll
    for (int mi = 0; mi < 4; mi++)
#pragma unroll
        for (int ni = 0; ni < 4; ni++) {
            int r0 = wm * 64 + mi * 16 + (lid >> 2);
            int cc = wn * 32 + ni * 8 + 2 * (lid & 3);
            Ep[r0 * 129 + cc]           = acc[mi][ni][0];
            Ep[r0 * 129 + cc + 1]       = acc[mi][ni][1];
            Ep[(r0 + 8) * 129 + cc]     = acc[mi][ni][2];
            Ep[(r0 + 8) * 129 + cc + 1] = acc[mi][ni][3];
        }
    __syncthreads();

    int row = tid >> 1, half = tid & 1;
    float* rp = Ep + row * 129 + half * 64;

    if (MODE == 1) {
        float s = 0.f, s2 = 0.f;
#pragma unroll 4
        for (int i = 0; i < 64; i++) {
            float x = rp[i] + bias[half * 64 + i];
            s += x; s2 += x * x;
        }
        s  += __shfl_xor_sync(0xffffffffu, s,  1);
        s2 += __shfl_xor_sync(0xffffffffu, s2, 1);
        float mu  = s * (1.f / 128.f);
        float var = s2 * (1.f / 128.f) - mu * mu;
        float rs  = rsqrtf(var + 1e-5f);
        __nv_bfloat16* oH = g_hmH + (size_t)(m0 + row) * 128 + half * 64;
        __nv_bfloat16* oL = g_hmL + (size_t)(m0 + row) * 128 + half * 64;
#pragma unroll 1
        for (int i = 0; i < 16; i++) {
            __nv_bfloat16 hb[4], lb[4];
#pragma unroll
            for (int j = 0; j < 4; j++) {
                int cc = half * 64 + i * 4 + j;
                float x  = rp[i * 4 + j] + bias[cc];
                float xn = (x - mu) * rs * gain[cc] + beta[cc];
                float o  = 0.5f * xn * (1.f + erff(xn * 0.70710678118654752f));
                __nv_bfloat16 hh = __float2bfloat16_rn(o);
                hb[j] = hh;
                lb[j] = __float2bfloat16_rn(o - __bfloat162float(hh));
            }
            *(uint2*)(oH + i * 4) = *(uint2*)hb;
            *(uint2*)(oL + i * 4) = *(uint2*)lb;
        }
    } else { // MODE 2
        float s = 0.f;
#pragma unroll 4
        for (int i = 0; i < 64; i++) {
            int gc = n0 + half * 64 + i;
            float x = (rp[i] + bias[gc]) * gain[gc];
            s += fabsf(x);
        }
        s += __shfl_xor_sync(0xffffffffu, s, 1);
        float rsc = 1.f / (s + 1e-8f);
#pragma unroll 4
        for (int i = 0; i < 64; i++) {
            int gc = n0 + half * 64 + i;
            rp[i] = (rp[i] + bias[gc]) * gain[gc] * rsc;
        }
        __syncthreads();
        float* dst = g_hT + (size_t)((m0 >> 13) * 2 + (n0 >> 7)) * (128 * 8192) + (m0 & 8191);
#pragma unroll 1
        for (int ccs = 0; ccs < 16; ccs++) {
            int cc = wid * 16 + ccs;
            float* dp = dst + (size_t)cc * 8192;
#pragma unroll
            for (int sq = 0; sq < 4; sq++)
                dp[sq * 32 + lid] = Ep[(sq * 32 + lid) * 129 + cc];
        }
    }
}

// merged MODE0 + MODE1 launch (independent GEMMs share the grid)
__global__ __launch_bounds__(256, 2)
void k_mma01(const float* __restrict__ b1, const float* __restrict__ lng,
             const float* __restrict__ lnb)
{
    int bx = blockIdx.x;
    if (bx < 768) mma_body<0>(bx & 255, bx >> 8, nullptr, nullptr, nullptr, nullptr);
    else          mma_body<1>(bx - 768, 0, b1, lng, lnb, nullptr);
}
__global__ __launch_bounds__(256, 2)
void k_mma2(const float* __restrict__ b2, const float* __restrict__ ffs)
{
    mma_body<2>(blockIdx.x, blockIdx.y, b2, ffs, nullptr, nullptr);
}
__global__ __launch_bounds__(256, 2)
void k_mma3(float* __restrict__ out)
{
    mma_body<3>(blockIdx.x, 0, nullptr, nullptr, nullptr, out);
}

// ---------------- FFT recurrence + fused depthwise conv ----------------
__global__ __launch_bounds__(1024, 1)
void k_fftrec(const float* __restrict__ Bp, const float* __restrict__ cw,
              const float* __restrict__ cb) {
    extern __shared__ float2 sh[];
    __shared__ float s_w[1152];
    __shared__ float s_b[384];
    int b = blockIdx.x >> 7, d = blockIdx.x & 127;
    int t = threadIdx.x;
    if (t < 384) s_b[t] = cb[t];
    if (t >= 512 && t < 512 + 384) {
        int i = t - 512;
        s_w[i] = cw[i]; s_w[i + 384] = cw[i + 384]; s_w[i + 768] = cw[i + 768];
    }
    __syncthreads();

    const float* X = g_x + (size_t)b * (8192 * 384);
    const int fbase = d * 24576;
    const int FMAX = 8192 * 384;

    auto ztap = [&](int j) -> float {
        int f = fbase + j;
        int c = j % 384;
        float a = s_b[c] + s_w[3 * c + 1] * X[f];
        if (f >= 384)       a += s_w[3 * c]     * X[f - 384];
        if (f + 384 < FMAX) a += s_w[3 * c + 2] * X[f + 384];
        return a;
    };

    float vv[8];
#pragma unroll
    for (int k = 0; k < 8; k++) vv[k] = ztap(16384 + t + k * 1024);

    for (int it = 0; it < 2; it++) {
        const float* h = g_hT + (size_t)((b * 2 + it) * 128 + d) * 8192;

        {
            float2 x[16];
#pragma unroll
            for (int r = 0; r < 4; r++) {
                float2 x0 = make_float2(vv[r],     h[t + 1024 * r]);
                float2 x1 = make_float2(vv[r + 4], h[t + 1024 * r + 4096]);
                float2 W1 = g_tw[t + 1024 * r];
                float2 W2 = make_float2(W1.y, -W1.x);
                float2 W3 = cmul(W1, W1);
                float2 t02m = cmul(x0, W1);
                float2 t13m = cmul(x1, W2);
                x[r]      = cadd(x0, x1);
                x[r + 4]  = cmul(csub(x0, x1), W3);
                x[r + 8]  = cadd(t02m, t13m);
                x[r + 12] = cmul(csub(t02m, t13m), W3);
            }
            float2 Wl2 = g_tw[4 * t];
#pragma unroll
            for (int q = 0; q < 4; q++) fwd4(x[4 * q], x[4 * q + 1], x[4 * q + 2], x[4 * q + 3], Wl2);
#pragma unroll
            for (int r = 0; r < 16; r++) sh[PD(t + 1024 * r)] = x[r];
        }
        __syncthreads();

        {
            int blk = t >> 6, off = t & 63;
            int base = blk * 1024 + off;
            float2 x[16];
#pragma unroll
            for (int r = 0; r < 16; r++) x[r] = sh[PD(base + 64 * r)];
#pragma unroll
            for (int r = 0; r < 4; r++) fwd4(x[r], x[r + 4], x[r + 8], x[r + 12], g_tw[16 * off + 1024 * r]);
            float2 Wl2 = g_tw[64 * off];
#pragma unroll
            for (int q = 0; q < 4; q++) fwd4(x[4 * q], x[4 * q + 1], x[4 * q + 2], x[4 * q + 3], Wl2);
#pragma unroll
            for (int r = 0; r < 16; r++) sh[PD(base + 64 * r)] = x[r];
        }
        __syncthreads();

        {
            int blk = t >> 2, off = t & 3;
            int base = blk * 64 + off;
            float2 x[16];
#pragma unroll
            for (int r = 0; r < 16; r++) x[r] = sh[PD(base + 4 * r)];
#pragma unroll
            for (int r = 0; r < 4; r++) fwd4(x[r], x[r + 4], x[r + 8], x[r + 12], g_tw[256 * off + 1024 * r]);
            float2 Wl2 = g_tw[1024 * off];
#pragma unroll
            for (int q = 0; q < 4; q++) fwd4(x[4 * q], x[4 * q + 1], x[4 * q + 2], x[4 * q + 3], Wl2);
#pragma unroll
            for (int r = 0; r < 16; r++) sh[PD(base + 4 * r)] = x[r];
        }
        __syncthreads();

#pragma unroll
        for (int k = 0; k < 4; k++) {
            int q4 = (t + 1024 * k) * 4;
            float2 y0 = sh[PD(q4)], y1 = sh[PD(q4 + 1)], y2 = sh[PD(q4 + 2)], y3 = sh[PD(q4 + 3)];
            fwd4(y0, y1, y2, y3, make_float2(1.f, 0.f));
            sh[PD(q4)] = y0; sh[PD(q4 + 1)] = y1; sh[PD(q4 + 2)] = y2; sh[PD(q4 + 3)] = y3;
        }
        __syncthreads();

        {
            int e0 = t << 4;
            float2 x[16];
#pragma unroll
            for (int r = 0; r < 16; r++) x[r] = sh[PD(e0 + r)];
#pragma unroll
            for (int r = 0; r < 16; r++) {
                int p  = e0 + r;
                int kk = __brev(p) >> 18;
                int k2 = (16384 - kk) & 16383;
                int p2 = __brev(k2) >> 18;
                float2 Q = sh[PD(p2)];
                float2 P = x[r];
                float vx = 0.5f * (P.x + Q.x), vy = 0.5f * (P.y - Q.y);
                float hx = 0.5f * (P.y + Q.y), hy = 0.5f * (Q.x - P.x);
                x[r] = make_float2(vx * hx - vy * hy, vx * hy + vy * hx);
            }
#pragma unroll
            for (int q = 0; q < 4; q++) inv4(x[4 * q], x[4 * q + 1], x[4 * q + 2], x[4 * q + 3], make_float2(1.f, 0.f));
#pragma unroll
            for (int r = 0; r < 4; r++) inv4(x[r], x[r + 4], x[r + 8], x[r + 12], g_tw[1024 * r]);
            __syncthreads();
#pragma unroll
            for (int r = 0; r < 16; r++) sh[PD(e0 + r)] = x[r];
        }
        __syncthreads();

        {
            int blk = t >> 4, off = t & 15;
            int base = blk * 256 + off;
            float2 x[16];
#pragma unroll
            for (int r = 0; r < 16; r++) x[r] = sh[PD(base + 16 * r)];
            float2 wA = g_tw[256 * off];
#pragma unroll
            for (int q = 0; q < 4; q++) inv4(x[4 * q], x[4 * q + 1], x[4 * q + 2], x[4 * q + 3], wA);
#pragma unroll
            for (int r = 0; r < 4; r++) inv4(x[r], x[r + 4], x[r + 8], x[r + 12], g_tw[64 * off + 1024 * r]);
#pragma unroll
            for (int r = 0; r < 16; r++) sh[PD(base + 16 * r)] = x[r];
        }
        __syncthreads();

        {
            int blk = t >> 8, off = t & 255;
            int base = blk * 4096 + off;
            float2 x[16];
#pragma unroll
            for (int r = 0; r < 16; r++) x[r] = sh[PD(base + 256 * r)];
            float2 wA = g_tw[16 * off];
#pragma unroll
            for (int q = 0; q < 4; q++) inv4(x[4 * q], x[4 * q + 1], x[4 * q + 2], x[4 * q + 3], wA);
#pragma unroll
            for (int r = 0; r < 4; r++) inv4(x[r], x[r + 4], x[r + 8], x[r + 12], g_tw[4 * off + 1024 * r]);
#pragma unroll
            for (int r = 0; r < 16; r++) sh[PD(base + 256 * r)] = x[r];
        }
        __syncthreads();

        {
            float Bn = Bp[it * 128 + d];
#pragma unroll
            for (int jj = 0; jj < 4; jj++) {
                int j = t + jj * 1024;
                float2 x0 = sh[PD(j)];
                float2 x1 = sh[PD(j + 4096)];
                float2 x2 = sh[PD(j + 8192)];
                float2 x3 = sh[PD(j + 12288)];
                float2 w   = g_tw[j];
                float2 cw2 = make_float2(w.x, -w.y);
                float2 cw1 = cmul(cw2, cw2);
                float2 cw3 = make_float2(-cw2.y, cw2.x);
                float2 b1 = cmul(x1, cw1);
                float2 b3 = cmul(x3, cw1);
                float2 u0 = cadd(x0, b1), u1 = csub(x0, b1);
                float2 u2 = cadd(x2, b3), u3 = csub(x2, b3);
                float y0x = u0.x + (u2.x * cw2.x - u2.y * cw2.y);
                float y1x = u1.x + (u3.x * cw3.x - u3.y * cw3.y);
                float z0 = ztap(it * 8192 + j);
                float z1 = ztap(it * 8192 + j + 4096);
                vv[jj]     = z0 * (y0x * SCALE_U + Bn * vv[jj]);
                vv[jj + 4] = z1 * (y1x * SCALE_U + Bn * vv[jj + 4]);
            }
        }
        __syncthreads();
    }
    __nv_bfloat16* vH = g_vH + (size_t)(b * 128 + d) * 8192;
    __nv_bfloat16* vL = g_vL + (size_t)(b * 128 + d) * 8192;
#pragma unroll
    for (int k = 0; k < 8; k++) {
        float val = vv[k];
        __nv_bfloat16 hh = __float2bfloat16_rn(val);
        vH[t + k * 1024] = hh;
        vL[t + k * 1024] = __float2bfloat16_rn(val - __bfloat162float(hh));
    }
}

extern "C" void kernel_launch(void* const* d_in, const int* in_sizes, int n_in,
                              void* d_out, int out_size) {
    const float* emb = (const float*)d_in[0];
    const float* Wp  = (const float*)d_in[1];
    const float* cw  = (const float*)d_in[2];
    const float* cb  = (const float*)d_in[3];
    const float* W1  = (const float*)d_in[4];
    const float* b1  = (const float*)d_in[5];
    const float* lng = (const float*)d_in[6];
    const float* lnb = (const float*)d_in[7];
    const float* W2  = (const float*)d_in[8];
    const float* b2  = (const float*)d_in[9];
    const float* ffs = (const float*)d_in[10];
    const float* op  = (const float*)d_in[11];
    const float* Bp  = (const float*)d_in[12];
    const int*   pos = (const int*)d_in[13];
    float* out = (float*)d_out;

    const int FFT_SMEM = 139776;
    const int MMA_SMEM_BIG   = 128 * 129 * 4;  // 66048 (modes 0/1 merged, mode 2)
    const int MMA_SMEM_SMALL = 2 * STG;        // 43008 (mode 3)
    cudaFuncSetAttribute(k_fftrec, cudaFuncAttributeMaxDynamicSharedMemorySize, FFT_SMEM);
    cudaFuncSetAttribute(k_mma01, cudaFuncAttributeMaxDynamicSharedMemorySize, MMA_SMEM_BIG);
    cudaFuncSetAttribute(k_mma2,  cudaFuncAttributeMaxDynamicSharedMemorySize, MMA_SMEM_BIG);
    cudaFuncSetAttribute(k_mma3,  cudaFuncAttributeMaxDynamicSharedMemorySize, MMA_SMEM_SMALL);

    k_init<<<8672, 256>>>(emb, pos, Wp, W1, W2, op);
    k_mma01<<<1024, 256, MMA_SMEM_BIG>>>(b1, lng, lnb);
    k_mma2<<<dim3(256, 2), 256, MMA_SMEM_BIG>>>(b2, ffs);
    k_fftrec<<<512, 1024, FFT_SMEM>>>(Bp, cw, cb);
    k_mma3<<<256, 256, MMA_SMEM_SMALL>>>(out);
}